// round 11
// baseline (speedup 1.0000x reference)
#include <cuda_runtime.h>
#include <math.h>

// predicts/targets (2,4,64,256,256) f32, masks (2,1,64,256,256) f32 -> scalar f32.
// Identities (validated R2..R9, rel_err ~1e-7):
//   omega_pred - omega_trgt = vorticity(scale*(P-T));  scale/(2*delta)=1
//   voxel counts & contributes <=> all 27 masks in 3x3x3 neighborhood == 1
namespace {
constexpr int Bn = 2, Cn = 4, Dn = 64, Hn = 256, Wn = 256;
constexpr long long CH = (long long)Dn * Hn * Wn;
constexpr int TY  = 7;                   // output rows per block
constexpr int RWS = 9;                   // staged rows (TY + 2 halo)
constexpr int NYT = 37;                  // 37*7 = 259 >= 254
constexpr int ZC  = 4;                   // z-chunks per batch (16,16,16,14)
constexpr int NBLK = NYT * 2 * ZC;       // 296 = 2 blocks/SM * 148 SMs
constexpr int PLF  = RWS * Wn;           // elems per staged plane (2304)
// dynamic smem layout (bytes)
constexpr int OFF_U  = 0;                       // 3 f32 planes (z-ring)
constexpr int OFF_V  = OFF_U  + 3 * PLF * 4;    // 3 f32 planes
constexpr int OFF_W  = OFF_V  + 3 * PLF * 4;    // 2 f32 planes
constexpr int OFF_M  = OFF_W  + 2 * PLF * 4;    // 3 u8 planes (mask 0/1)
constexpr int OFF_CP = OFF_M  + 3 * PLF;        // 2 u8 planes (3z column AND)
constexpr int SMEM_BYTES = OFF_CP + 2 * PLF + 16;  // +16 pad for edge cp[o+4] read
}

__device__ float        g_psum[NBLK];
__device__ unsigned int g_pcnt[NBLK];
__device__ unsigned int g_ticket = 0;

__device__ __forceinline__ float fj(const float4& v, int j) {
    return j == 0 ? v.x : j == 1 ? v.y : j == 2 ? v.z : v.w;
}

__global__ __launch_bounds__(512, 2)
void k_main(const float* __restrict__ P,
            const float* __restrict__ T,
            const float* __restrict__ M,
            float* __restrict__ out) {
    extern __shared__ unsigned char smem[];
    float*         sU  = (float*)(smem + OFF_U);
    float*         sV  = (float*)(smem + OFF_V);
    float*         sW  = (float*)(smem + OFF_W);
    unsigned char* sM  = smem + OFF_M;
    unsigned char* sCP = smem + OFF_CP;

    const int tid = threadIdx.x;
    const int b   = blockIdx.y / ZC;
    const int zi  = blockIdx.y % ZC;
    const int z0  = 1 + zi * 16;
    const int z1  = min(z0 + 15, Dn - 2);         // chunks: 16,16,16,14
    const int y0  = 1 + blockIdx.x * TY;

    const float* mb = M + (long long)b * CH;
    const float* uP = P + ((long long)b * Cn + 1) * CH;
    const float* uT = T + ((long long)b * Cn + 1) * CH;
    const float* vP = uP + CH;  const float* vT = uT + CH;
    const float* wP = vP + CH;  const float* wT = vT + CH;

    // Stage one float4 slot of plane zz into the rings (+ optional w, CP).
    auto stage = [&](int slot, int zz, int suvm, int sw2, bool doW,
                     bool doCP, int mszm, int msz, int mcp) {
        const int r  = slot >> 6;
        const int x4 = (slot & 63) << 2;
        const int yy = min(y0 - 1 + r, Hn - 1);
        const long long base = ((long long)zz * Hn + yy) * Wn + x4;
        const int ro = r * Wn + x4;

        float4 a = *(const float4*)(uP + base);
        float4 c = *(const float4*)(uT + base);
        float4 a2 = *(const float4*)(vP + base);
        float4 c2 = *(const float4*)(vT + base);
        *(float4*)(sU + suvm * PLF + ro) = make_float4(a.x - c.x, a.y - c.y, a.z - c.z, a.w - c.w);
        *(float4*)(sV + suvm * PLF + ro) = make_float4(a2.x - c2.x, a2.y - c2.y, a2.z - c2.z, a2.w - c2.w);
        if (doW) {
            a = *(const float4*)(wP + base);
            c = *(const float4*)(wT + base);
            *(float4*)(sW + sw2 * PLF + ro) = make_float4(a.x - c.x, a.y - c.y, a.z - c.z, a.w - c.w);
        }
        const float4 mv = *(const float4*)(mb + base);
        const unsigned mw = (mv.x > 0.5f ? 1u : 0u)
                          | (mv.y > 0.5f ? 1u : 0u) << 8
                          | (mv.z > 0.5f ? 1u : 0u) << 16
                          | (mv.w > 0.5f ? 1u : 0u) << 24;
        *(unsigned*)(sM + suvm * PLF + ro) = mw;
        if (doCP) {
            const unsigned cpw = mw & *(const unsigned*)(sM + mszm * PLF + ro)
                                    & *(const unsigned*)(sM + msz  * PLF + ro);
            *(unsigned*)(sCP + mcp * PLF + ro) = cpw;
        }
    };
    const bool extra = (tid & 7) == 0;            // 64 extra slots spread over all warps
    const int  xslot = 512 + (tid >> 3);

    // ---- prologue: planes z0-1, z0 of u,v,m ; plane z0 of w ----
    #pragma unroll
    for (int k = 0; k < 2; ++k) {
        const int zz = z0 - 1 + k;
        stage(tid, zz, zz % 3, zz & 1, k == 1, false, 0, 0, 0);
        if (extra) stage(xslot, zz, zz % 3, zz & 1, k == 1, false, 0, 0, 0);
    }
    __syncthreads();

    float fs  = 0.f;
    int   cnt = 0;

    for (int z = z0; z <= z1; ++z) {
        const int snew = (z + 1) % 3;
        const int szm  = (z - 1) % 3, sz = z % 3;
        const int swz  = z & 1, swN = (z + 1) & 1, scp = z & 1;

        // ---- stage plane z+1 + CP(z), balanced across warps ----
        stage(tid, z + 1, snew, swN, true, true, szm, sz, scp);
        if (extra) stage(xslot, z + 1, snew, swN, true, true, szm, sz, scp);
        __syncthreads();

        // ---- consume plane z: 448 threads x one 4-wide x-group ----
        if (tid < 448) {
            const int r  = (tid >> 6) + 1;        // 1..7
            const int g  = tid & 63;
            const int x4 = g << 2;
            const int y  = y0 - 1 + r;
            if (y <= Hn - 2) {
                const unsigned char* cp = sCP + scp * PLF;
                unsigned okw = 0x01010101u;
                #pragma unroll
                for (int dr = -1; dr <= 1; ++dr) {
                    const int o = (r + dr) * Wn + x4;
                    const unsigned Wc = *(const unsigned*)(cp + o);
                    const unsigned lw = (Wc << 8) | (unsigned)cp[o - 1];
                    const unsigned rw = (Wc >> 8) | ((unsigned)cp[o + 4] << 24);
                    okw &= Wc & lw & rw;          // byte j: AND of x4+j-1 .. x4+j+1
                }
                if (g == 0)  okw &= 0xFFFFFF00u;  // x=0 invalid
                if (g == 63) okw &= 0x00FFFFFFu;  // x=255 invalid
                if (okw) {                        // ~21% of groups: load + compute
                    cnt += __popc(okw);
                    const int ro = r * Wn + x4;
                    const float* uZ = sU + sz * PLF;
                    const float4 uyp = *(const float4*)(uZ + ro + Wn);
                    const float4 uym = *(const float4*)(uZ + ro - Wn);
                    const float4 uzp = *(const float4*)(sU + snew * PLF + ro);
                    const float4 uzm = *(const float4*)(sU + szm  * PLF + ro);
                    const float* wZ = sW + swz * PLF;
                    const float4 wyp = *(const float4*)(wZ + ro + Wn);
                    const float4 wym = *(const float4*)(wZ + ro - Wn);
                    const float4 wl  = *(const float4*)(wZ + ro - 4);
                    const float4 wc  = *(const float4*)(wZ + ro);
                    const float4 wr  = *(const float4*)(wZ + ro + 4);
                    const float* vZ = sV + sz * PLF;
                    const float4 vl  = *(const float4*)(vZ + ro - 4);
                    const float4 vc  = *(const float4*)(vZ + ro);
                    const float4 vr  = *(const float4*)(vZ + ro + 4);
                    const float4 vzp = *(const float4*)(sV + snew * PLF + ro);
                    const float4 vzm = *(const float4*)(sV + szm  * PLF + ro);
                    const float xw[6] = {wl.w, wc.x, wc.y, wc.z, wc.w, wr.x};
                    const float xv[6] = {vl.w, vc.x, vc.y, vc.z, vc.w, vr.x};
                    #pragma unroll
                    for (int j = 0; j < 4; ++j) {
                        if ((okw >> (8 * j)) & 1u) {
                            const float dyU = fj(uyp, j) - fj(uym, j);
                            const float dzU = fj(uzp, j) - fj(uzm, j);
                            const float dyW = fj(wyp, j) - fj(wym, j);
                            const float dxW = xw[j + 2] - xw[j];
                            const float dxV = xv[j + 2] - xv[j];
                            const float dzV = fj(vzp, j) - fj(vzm, j);
                            const float ox = dyW - dzV;
                            const float oy = dzU - dxW;
                            const float oz = dxV - dyU;
                            fs += sqrtf(ox * ox + oy * oy + oz * oz);
                        }
                    }
                }
            }
        }
        __syncthreads();   // next stage overwrites u/v/m slot (z-1)%3, w slot z&1, CP scp^1
    }

    // ---- block reduction (16 warps) -> partial; last block finalizes ----
    #pragma unroll
    for (int off = 16; off; off >>= 1) {
        fs  += __shfl_down_sync(0xffffffffu, fs,  off);
        cnt += __shfl_down_sync(0xffffffffu, cnt, off);
    }
    __shared__ float ws[16];
    __shared__ int   wc2[16];
    __shared__ bool  sLast;
    const int wid = tid >> 5, lid = tid & 31;
    if (lid == 0) { ws[wid] = fs; wc2[wid] = cnt; }
    __syncthreads();
    if (wid == 0) {
        fs  = (lid < 16) ? ws[lid]  : 0.f;
        cnt = (lid < 16) ? wc2[lid] : 0;
        #pragma unroll
        for (int off = 8; off; off >>= 1) {
            fs  += __shfl_down_sync(0xffffffffu, fs,  off);
            cnt += __shfl_down_sync(0xffffffffu, cnt, off);
        }
        if (lid == 0) {
            const int slot = blockIdx.y * NYT + blockIdx.x;
            g_psum[slot] = fs;
            g_pcnt[slot] = (unsigned)cnt;
            __threadfence();
            const unsigned t = atomicAdd(&g_ticket, 1u);
            sLast = (t == NBLK - 1);
        }
    }
    __syncthreads();

    if (sLast) {
        // Deterministic final reduce: fixed order over 296 slots, double accum.
        double             s = (tid < NBLK) ? (double)__ldcg(&g_psum[tid]) : 0.0;
        unsigned long long c = (tid < NBLK) ? (unsigned long long)__ldcg(&g_pcnt[tid]) : 0ull;
        #pragma unroll
        for (int off = 16; off; off >>= 1) {
            s += __shfl_down_sync(0xffffffffu, s, off);
            c += __shfl_down_sync(0xffffffffu, c, off);
        }
        __shared__ double             ds[16];
        __shared__ unsigned long long dc[16];
        if (lid == 0) { ds[wid] = s; dc[wid] = c; }
        __syncthreads();
        if (wid == 0) {
            s = (lid < 16) ? ds[lid] : 0.0;
            c = (lid < 16) ? dc[lid] : 0ull;
            #pragma unroll
            for (int off = 8; off; off >>= 1) {
                s += __shfl_down_sync(0xffffffffu, s, off);
                c += __shfl_down_sync(0xffffffffu, c, off);
            }
            if (lid == 0) {
                out[0] = (float)(s / (double)c);
                g_ticket = 0;                     // reset for next graph replay
            }
        }
    }
}

extern "C" void kernel_launch(void* const* d_in, const int* in_sizes, int n_in,
                              void* d_out, int out_size) {
    const float* P = (const float*)d_in[0];
    const float* T = (const float*)d_in[1];
    const float* M = (const float*)d_in[2];
    float*       O = (float*)d_out;

    cudaFuncSetAttribute(k_main, cudaFuncAttributeMaxDynamicSharedMemorySize, SMEM_BYTES);
    k_main<<<dim3(NYT, 2 * ZC), 512, SMEM_BYTES>>>(P, T, M, O);
}